// round 5
// baseline (speedup 1.0000x reference)
#include <cuda_runtime.h>

// CutStripes: out[b, :, t, :] = x[perm[b], :, t, :] if t falls inside any of 4
// stripes [bgn[b,s], bgn[b,s]+distance[b,s]), else x[b, :, t, :].
// Shapes: B=128, C=1, T=2048, F=128, STRIPES=4.
//
// R4: register path (R2) + streaming store hints. R3 proved MLP is not the
// limiter (cp.async MLP=8 == register path bandwidth), so the binding
// constraint is L2/DRAM efficiency of the mixed read/write stream. st.global.cs
// (evict-first) keeps the touch-once write stream from thrashing L2, protecting
// the read stream and the ~6% of rows read twice (b and perm-consumer).
// All-int indexing (max idx 8.4M < 2^31) shortens address IMAD chains.

#define T_DIM         2048
#define F4            32        // 128 floats / 4
#define STRIPES       4
#define ROWS_PER_WARP 8
#define WARPS_PER_BLK 8

__global__ __launch_bounds__(256) void cutstripes_kernel(
    const float4* __restrict__ x,
    const int*    __restrict__ perm,
    const int*    __restrict__ bgn,
    const int*    __restrict__ dist,
    float4*       __restrict__ out)
{
    const int warp = (blockIdx.x * blockDim.x + threadIdx.x) >> 5;  // row-group id
    const int lane = threadIdx.x & 31;

    // Each group = 8 consecutive t rows of one batch b.
    const int b  = warp >> 8;                          // / (T_DIM/ROWS_PER_WARP)
    const int t0 = (warp & 255) * ROWS_PER_WARP;

    // Lane l checks row k = l>>2, stripe s = l&3 -> one ballot covers 8 rows.
    const int k = lane >> 2;
    const int s = lane & 3;
    const int lo = __ldg(&bgn[b * STRIPES + s]);
    const int hi = lo + __ldg(&dist[b * STRIPES + s]);
    const bool in_stripe = ((t0 + k) >= lo) && ((t0 + k) < hi);
    const unsigned m = __ballot_sync(0xFFFFFFFFu, in_stripe);
    const int pb = __ldg(&perm[b]);

    // Front-batched loads: 8 independent LDG.128 (int indexing, fits 2^31).
    float4 v[ROWS_PER_WARP];
    #pragma unroll
    for (int r = 0; r < ROWS_PER_WARP; r++) {
        const int src = ((m >> (4 * r)) & 0xF) ? pb : b;
        const int src_idx = ((src << 11) | (t0 + r)) * F4 + lane;
        v[r] = x[src_idx];
    }

    // Streaming stores: evict-first so the write stream doesn't thrash L2.
    const int dst_base = ((b << 11) | t0) * F4 + lane;
    #pragma unroll
    for (int r = 0; r < ROWS_PER_WARP; r++) {
        __stcs(&out[dst_base + r * F4], v[r]);
    }
}

extern "C" void kernel_launch(void* const* d_in, const int* in_sizes, int n_in,
                              void* d_out, int out_size)
{
    const float4* x    = (const float4*)d_in[0];   // (128,1,2048,128) fp32
    const int*    perm = (const int*)   d_in[1];   // (128,)
    const int*    bgn  = (const int*)   d_in[2];   // (128,4)
    const int*    dist = (const int*)   d_in[3];   // (128,4)
    float4*       out  = (float4*)d_out;

    const int rows   = 128 * T_DIM;                   // 262144
    const int warps  = rows / ROWS_PER_WARP;          // 32768
    const int blocks = warps / WARPS_PER_BLK;         // 4096

    cutstripes_kernel<<<blocks, 256>>>(x, perm, bgn, dist, out);
}